// round 17
// baseline (speedup 1.0000x reference)
#include <cuda_runtime.h>
#include <cuda_fp16.h>
#include <cstdint>
#include <math.h>

// ---------------- problem constants ----------------
#define BATCH 2
#define SEQ   2048
#define DMODEL 2048
#define NHEAD 16
#define HDIM  128
#define RQ    1536
#define RKV   512
#define MTOT  (BATCH*SEQ)          // 4096

// ---------------- scratch (allocation-free: __device__ globals) ----------------
__device__ __half g_xq[(size_t)MTOT * RQ];             // X @ Wq_down^T (fp16)
__device__ __half g_q [(size_t)MTOT * DMODEL];         // Q (fp16, for flash)
__device__ __half g_c [(size_t)MTOT * RKV];            // latent C (fp16)
__device__ __half g_k [(size_t)BATCH*NHEAD*SEQ*HDIM];  // K [b,h,s,d] (fp16)
__device__ __half g_v [(size_t)BATCH*NHEAD*SEQ*HDIM];  // V [b,h,s,d] (fp16)
__device__ __half g_vt[(size_t)BATCH*NHEAD*HDIM*SEQ];  // V^T [b,h,d,s] (fp16)
__device__ __half g_o [(size_t)MTOT * DMODEL];         // attn out (fp16, feeds Wo GEMM)
__device__ __half g_kuT[(size_t)NHEAD*HDIM*RKV];       // k_up^T (fp16)
__device__ __half g_vuT[(size_t)NHEAD*HDIM*RKV];       // v_up^T (fp16)
// fp16 copies of raw inputs
__device__ __half g_xr  [(size_t)MTOT * DMODEL];
__device__ __half g_wqdr[(size_t)RQ * DMODEL];
__device__ __half g_wqur[(size_t)DMODEL * RQ];
__device__ __half g_wkdr[(size_t)RKV * DMODEL];
__device__ __half g_wor [(size_t)DMODEL * DMODEL];

// ---------------- helpers ----------------
__device__ __forceinline__ uint32_t smem_u32(const void* p) {
    uint32_t a;
    asm("{ .reg .u64 t; cvta.to.shared.u64 t, %1; cvt.u32.u64 %0, t; }" : "=r"(a) : "l"(p));
    return a;
}
__device__ __forceinline__ void cp16(uint32_t saddr, const void* gaddr) {
    asm volatile("cp.async.cg.shared.global [%0], [%1], 16;" :: "r"(saddr), "l"(gaddr));
}
#define CP_COMMIT()  asm volatile("cp.async.commit_group;" ::: "memory")
#define CP_WAIT_1()  asm volatile("cp.async.wait_group 1;" ::: "memory")
#define CP_WAIT_0()  asm volatile("cp.async.wait_group 0;" ::: "memory")

// ldmatrix x4 (b16)
__device__ __forceinline__ void ldsm4(uint32_t& r0, uint32_t& r1, uint32_t& r2, uint32_t& r3,
                                      uint32_t saddr) {
    asm volatile("ldmatrix.sync.aligned.m8n8.x4.shared.b16 {%0,%1,%2,%3}, [%4];"
                 : "=r"(r0), "=r"(r1), "=r"(r2), "=r"(r3) : "r"(saddr));
}

// mma.sync m16n8k16 fp16: D = A(16x16 row) * B(8x16 col) + C, fp32 accum.
__device__ __forceinline__ void mma_f16(float& c0, float& c1, float& c2, float& c3,
                                        uint32_t a0, uint32_t a1, uint32_t a2, uint32_t a3,
                                        uint32_t b0, uint32_t b1) {
    asm volatile(
        "mma.sync.aligned.m16n8k16.row.col.f32.f16.f16.f32 "
        "{%0,%1,%2,%3}, {%4,%5,%6,%7}, {%8,%9}, {%0,%1,%2,%3};"
        : "+f"(c0), "+f"(c1), "+f"(c2), "+f"(c3)
        : "r"(a0), "r"(a1), "r"(a2), "r"(a3), "r"(b0), "r"(b1));
}

// ---------------- elementwise fp16 rounding copy ----------------
__global__ __launch_bounds__(256)
void round_half(const float* __restrict__ in, __half* __restrict__ out, long n4)
{
    long i = (long)blockIdx.x * blockDim.x + threadIdx.x;
    long stride = (long)gridDim.x * blockDim.x;
    for (; i < n4; i += stride) {
        float4 v = ((const float4*)in)[i];
        ((__half2*)out)[2*i]   = __floats2half2_rn(v.x, v.y);
        ((__half2*)out)[2*i+1] = __floats2half2_rn(v.z, v.w);
    }
}

// ---------------- fp16 tensor-core GEMM: C = A @ B^T (cp.async + ldmatrix) ----------------
// A [M,K], B [N,K] row-major __half. CTA 128x128, BK=32, 4 warps, warp tile 64x64.
// OM: 0 = fp32 out, 2 = fp16 out.
// Dual-output batching: z >= nz1 switches to (B2, C2) with z -= nz1.
#define STH 40                       // row stride in halves (80 B)
#define GEMM_BUF_HALVES (128 * STH)
#define GEMM_SMEM_BYTES (4 * GEMM_BUF_HALVES * 2)   // 40960 B

template<int OM>
__global__ __launch_bounds__(128, 2)
void gemm_tc(const __half* __restrict__ A, const __half* __restrict__ B,
             void* __restrict__ C,
             const __half* __restrict__ B2, void* __restrict__ C2, int nz1,
             int M, int N, int K,
             long sA, long sB, long sC, int hmod)
{
    extern __shared__ __half sh[];
    const uint32_t sbase = smem_u32(sh);

    const int tid = threadIdx.x;
    const int wid = tid >> 5, lane = tid & 31;
    const int g = lane >> 2, t = lane & 3;
    const int quad = lane >> 3, rin = lane & 7;
    int z = blockIdx.z;
    const __half* Bp = B;
    void* Cv = C;
    if (z >= nz1) { Bp = B2; Cv = C2; z -= nz1; }
    const __half* Ab = A + (long)(z / hmod) * sA;
    const __half* Bb = Bp + (long)(z % hmod) * sB;
    const int m0 = blockIdx.y * 128;
    const int n0 = blockIdx.x * 128;

    const int wm = (wid & 1) * 64;
    const int wn = (wid >> 1) * 64;

    const uint32_t aoff_t = (uint32_t)((wm + (quad & 1) * 8 + rin) * STH + (quad >> 1) * 8);
    const uint32_t boff_t = (uint32_t)((wn + (quad >> 1) * 8 + rin) * STH + (quad & 1) * 8);

    float acc[4][8][4];
    #pragma unroll
    for (int m = 0; m < 4; m++)
        #pragma unroll
        for (int n = 0; n < 8; n++)
            #pragma unroll
            for (int r = 0; r < 4; r++) acc[m][n][r] = 0.f;

    const int lrow = tid >> 2;
    const int lc8  = (tid & 3) * 8;

    auto issue = [&](int k0, int b) {
        const uint32_t abase = sbase + (uint32_t)b * (2u * GEMM_BUF_HALVES * 2u);
        const uint32_t bbase = abase + GEMM_BUF_HALVES * 2u;
        #pragma unroll
        for (int p = 0; p < 4; p++) {
            const int row = lrow + p * 32;
            const uint32_t so = (uint32_t)(row * STH + lc8) * 2u;
            cp16(abase + so, Ab + (long)(m0 + row) * K + k0 + lc8);
            cp16(bbase + so, Bb + (long)(n0 + row) * K + k0 + lc8);
        }
        CP_COMMIT();
    };

    const int KT = K >> 5;
    issue(0, 0);

    for (int kt = 0; kt < KT; kt++) {
        if (kt + 1 < KT) { issue((kt + 1) << 5, (kt + 1) & 1); CP_WAIT_1(); }
        else             { CP_WAIT_0(); }
        __syncthreads();

        const uint32_t abuf = sbase + (uint32_t)(kt & 1) * (2u * GEMM_BUF_HALVES * 2u);
        const uint32_t bbuf = abuf + GEMM_BUF_HALVES * 2u;
        const uint32_t aaddr = abuf + aoff_t * 2u;
        const uint32_t baddr = bbuf + boff_t * 2u;

        #pragma unroll
        for (int ks = 0; ks < 2; ks++) {
            const uint32_t kk = (uint32_t)(ks * 16);
            uint32_t af[4][4], bf[8][2];
            #pragma unroll
            for (int m = 0; m < 4; m++)
                ldsm4(af[m][0], af[m][1], af[m][2], af[m][3],
                      aaddr + (uint32_t)(m * 16 * STH + kk) * 2u);
            #pragma unroll
            for (int np = 0; np < 4; np++)
                ldsm4(bf[2*np][0], bf[2*np][1], bf[2*np+1][0], bf[2*np+1][1],
                      baddr + (uint32_t)(np * 16 * STH + kk) * 2u);
            #pragma unroll
            for (int m = 0; m < 4; m++)
                #pragma unroll
                for (int n = 0; n < 8; n++)
                    mma_f16(acc[m][n][0], acc[m][n][1], acc[m][n][2], acc[m][n][3],
                            af[m][0], af[m][1], af[m][2], af[m][3],
                            bf[n][0], bf[n][1]);
        }
        __syncthreads();
    }

    #pragma unroll
    for (int m = 0; m < 4; m++) {
        const long row0 = m0 + wm + m * 16 + g;
        #pragma unroll
        for (int n = 0; n < 8; n++) {
            const int col = n0 + wn + n * 8 + 2 * t;
            if constexpr (OM == 2) {
                __half* Cb = (__half*)Cv + (long)z * sC;
                *(__half2*)(Cb + row0 * N + col) =
                    __floats2half2_rn(acc[m][n][0], acc[m][n][1]);
                *(__half2*)(Cb + (row0 + 8) * N + col) =
                    __floats2half2_rn(acc[m][n][2], acc[m][n][3]);
            } else {
                float* Cb = (float*)Cv + (long)z * sC;
                *(float2*)(Cb + row0 * N + col)       = make_float2(acc[m][n][0], acc[m][n][1]);
                *(float2*)(Cb + (row0 + 8) * N + col) = make_float2(acc[m][n][2], acc[m][n][3]);
            }
        }
    }
}

// ---------------- transpose [H, RKV, HDIM] -> [H, HDIM, RKV], fp16 on store ----------------
__global__ __launch_bounds__(256)
void transpose_up(const float* __restrict__ in, __half* __restrict__ out)
{
    __shared__ float t[32][33];
    const int h = blockIdx.z;
    const int r0 = blockIdx.y * 32;
    const int c0 = blockIdx.x * 32;
    const int tx = threadIdx.x & 31, ty0 = threadIdx.x >> 5;
    const float* ip = in + (long)h * RKV * HDIM;
    __half* op = out + (long)h * RKV * HDIM;
    #pragma unroll
    for (int r = 0; r < 4; r++) {
        int ty = ty0 + r * 8;
        t[ty][tx] = ip[(long)(r0 + ty) * HDIM + c0 + tx];
    }
    __syncthreads();
    #pragma unroll
    for (int r = 0; r < 4; r++) {
        int ty = ty0 + r * 8;
        op[(long)(c0 + ty) * RKV + r0 + tx] = __float2half_rn(t[tx][ty]);
    }
}

// ---------------- V transpose: [b,h,s,d] fp16 -> [b,h,d,s] fp16 ----------------
__global__ __launch_bounds__(256)
void transpose_v(const __half* __restrict__ in, __half* __restrict__ out)
{
    __shared__ __half t[32][33];
    const int z = blockIdx.z;                 // b*NHEAD + h
    const int s0 = blockIdx.y * 32;
    const int d0 = blockIdx.x * 32;
    const int tx = threadIdx.x & 31, ty0 = threadIdx.x >> 5;
    const __half* ip = in + (long)z * SEQ * HDIM;
    __half* op = out + (long)z * SEQ * HDIM;
    #pragma unroll
    for (int r = 0; r < 4; r++) {
        int ty = ty0 + r * 8;
        t[ty][tx] = ip[(long)(s0 + ty) * HDIM + d0 + tx];
    }
    __syncthreads();
    #pragma unroll
    for (int r = 0; r < 4; r++) {
        int ty = ty0 + r * 8;
        op[(long)(d0 + ty) * SEQ + s0 + tx] = t[tx][ty];
    }
}

// ---------------- fp16 tensor-core flash attention (ALiBi + causal) ----------------
// BM=128, BN=64, d=128; 8 warps, warp-local softmax. All operands fp16, fp32 softmax/accum.
// K natural [s,d]; V transposed [d,s] (so PV B-fragments pair along kv contiguously).
// K double-buffered, V single-buffered. Scalar 32-bit (half2) fragment loads, conflict-free.
#define FQH 136                      // Q,K row stride (halves)
#define FVH 72                       // Vt row stride
#define FPH 72                       // P row stride
#define FK_OFF (128*FQH)                       // 17408
#define FV_OFF (FK_OFF + 2*64*FQH)             // 34816
#define FP_OFF (FV_OFF + 128*FVH)              // 44032
#define FLASH_SMEM_HALVES (FP_OFF + 128*FPH)   // 53248
#define FLASH_SMEM_BYTES (FLASH_SMEM_HALVES * 2)  // 106496 B

__global__ __launch_bounds__(256, 2)
void flash_tc(const __half* __restrict__ Q, const __half* __restrict__ Kg,
              const __half* __restrict__ Vtg, __half* __restrict__ O)
{
    extern __shared__ __half sh2[];
    const uint32_t sbase = smem_u32(sh2);
    __half* Qs = sh2;                       // [128][136]
    __half* Ps = sh2 + FP_OFF;              // [128][72]

    const int bh = blockIdx.y;
    const int b  = bh >> 4, h = bh & 15;
    const int qt = gridDim.x - 1 - blockIdx.x;   // heavy tiles first
    const int q0 = qt * 128;
    const int tid = threadIdx.x;
    const int wid = tid >> 5, lane = tid & 31;
    const int g = lane >> 2, t = lane & 3;

    const float slope = exp2f(-0.5f * (float)(h + 1));
    const float scale = 0.08838834764831843f;

    const __half* Qbase  = Q   + ((long)(b*SEQ + q0)) * DMODEL + h*HDIM;
    const __half* Kbase  = Kg  + ((long)(b*NHEAD + h)) * SEQ * HDIM;
    const __half* Vtbase = Vtg + ((long)(b*NHEAD + h)) * (long)HDIM * SEQ;

    auto issueK = [&](int k0, int buf) {
        const uint32_t base = sbase + (uint32_t)(FK_OFF + buf * 64 * FQH) * 2u;
        #pragma unroll
        for (int p = 0; p < 4; p++) {
            int idx = tid + p*256;
            int row = idx >> 4, c8 = (idx & 15) * 8;
            cp16(base + (uint32_t)(row*FQH + c8)*2u, Kbase + (long)(k0+row)*HDIM + c8);
        }
        CP_COMMIT();
    };
    auto issueV = [&](int k0) {
        const uint32_t base = sbase + (uint32_t)FV_OFF * 2u;
        #pragma unroll
        for (int p = 0; p < 4; p++) {
            int idx = tid + p*256;
            int row = idx >> 3, c8 = (idx & 7) * 8;   // row = d (0..127), col = kv chunk
            cp16(base + (uint32_t)(row*FVH + c8)*2u, Vtbase + (long)row*SEQ + k0 + c8);
        }
        CP_COMMIT();
    };

    // prologue group: Q tile (128x128 halves) + K0
    #pragma unroll
    for (int p = 0; p < 8; p++) {
        int idx = tid + p*256;
        int row = idx >> 4, c8 = (idx & 15) * 8;
        cp16(sbase + (uint32_t)(row*FQH + c8)*2u, Qbase + (long)row*DMODEL + c8);
    }
    {
        const uint32_t base = sbase + (uint32_t)FK_OFF * 2u;
        #pragma unroll
        for (int p = 0; p < 4; p++) {
            int idx = tid + p*256;
            int row = idx >> 4, c8 = (idx & 15) * 8;
            cp16(base + (uint32_t)(row*FQH + c8)*2u, Kbase + (long)row*HDIM + c8);
        }
        CP_COMMIT();
    }

    const int r0 = wid*16 + g, r1 = r0 + 8;
    const int qi0 = q0 + r0, qi1 = q0 + r1;

    float o[16][4];
    #pragma unroll
    for (int n = 0; n < 16; n++)
        #pragma unroll
        for (int r = 0; r < 4; r++) o[n][r] = 0.f;
    float m0 = -INFINITY, m1 = -INFINITY, l0 = 0.f, l1 = 0.f;

    const int ktmax = 2*qt + 1;
    for (int kt = 0; kt <= ktmax; kt++) {
        const int k0 = kt * 64;
        __syncthreads();
        issueV(k0);
        if (kt < ktmax) { issueK(k0 + 64, (kt + 1) & 1); CP_WAIT_1(); }
        else            { CP_WAIT_0(); }
        __syncthreads();

        const __half* Kh = sh2 + FK_OFF + (size_t)(kt & 1) * (64 * FQH);
        const __half* Vt = sh2 + FV_OFF;

        // S = Q @ K^T  (warp tile 16x64: 8 n-subtiles, 8 k16-steps over d=128)
        float s[8][4];
        #pragma unroll
        for (int n = 0; n < 8; n++)
            #pragma unroll
            for (int r = 0; r < 4; r++) s[n][r] = 0.f;
        #pragma unroll
        for (int ks = 0; ks < 8; ks++) {
            const int kk = ks * 16;
            uint32_t a0 = *(const uint32_t*)&Qs[r0*FQH + kk + 2*t];
            uint32_t a1 = *(const uint32_t*)&Qs[r1*FQH + kk + 2*t];
            uint32_t a2 = *(const uint32_t*)&Qs[r0*FQH + kk + 8 + 2*t];
            uint32_t a3 = *(const uint32_t*)&Qs[r1*FQH + kk + 8 + 2*t];
            #pragma unroll
            for (int n = 0; n < 8; n++) {
                const int nr = n*8 + g;
                uint32_t b0 = *(const uint32_t*)&Kh[nr*FQH + kk + 2*t];
                uint32_t b1 = *(const uint32_t*)&Kh[nr*FQH + kk + 8 + 2*t];
                mma_f16(s[n][0], s[n][1], s[n][2], s[n][3], a0, a1, a2, a3, b0, b1);
            }
        }

        // scale + ALiBi + causal; warp-local row max
        float rv0 = -INFINITY, rv1 = -INFINITY;
        #pragma unroll
        for (int n = 0; n < 8; n++) {
            const int kj = k0 + n*8 + 2*t;
            s[n][0] = (kj   <= qi0) ? fmaf(s[n][0], scale, -slope*(float)(qi0-kj))   : -INFINITY;
            s[n][1] = (kj+1 <= qi0) ? fmaf(s[n][1], scale, -slope*(float)(qi0-kj-1)) : -INFINITY;
            s[n][2] = (kj   <= qi1) ? fmaf(s[n][2], scale, -slope*(float)(qi1-kj))   : -INFINITY;
            s[n][3] = (kj+1 <= qi1) ? fmaf(s[n][3], scale, -slope*(float)(qi1-kj-1)) : -INFINITY;
            rv0 = fmaxf(rv0, fmaxf(s[n][0], s[n][1]));
            rv1 = fmaxf(rv1, fmaxf(s[n][2], s[n][3]));
        }
        rv0 = fmaxf(rv0, __shfl_xor_sync(0xffffffffu, rv0, 1));
        rv0 = fmaxf(rv0, __shfl_xor_sync(0xffffffffu, rv0, 2));
        rv1 = fmaxf(rv1, __shfl_xor_sync(0xffffffffu, rv1, 1));
        rv1 = fmaxf(rv1, __shfl_xor_sync(0xffffffffu, rv1, 2));
        const float m0n = fmaxf(m0, rv0), m1n = fmaxf(m1, rv1);
        const float al0 = __expf(m0 - m0n), al1 = __expf(m1 - m1n);
        m0 = m0n; m1 = m1n;
        float rs0 = 0.f, rs1 = 0.f;
        #pragma unroll
        for (int n = 0; n < 8; n++) {
            float p00 = __expf(s[n][0] - m0n), p01 = __expf(s[n][1] - m0n);
            float p10 = __expf(s[n][2] - m1n), p11 = __expf(s[n][3] - m1n);
            rs0 += p00 + p01; rs1 += p10 + p11;
            const int cn = n*8 + 2*t;
            *(__half2*)&Ps[r0*FPH + cn] = __floats2half2_rn(p00, p01);
            *(__half2*)&Ps[r1*FPH + cn] = __floats2half2_rn(p10, p11);
        }
        rs0 += __shfl_xor_sync(0xffffffffu, rs0, 1);
        rs0 += __shfl_xor_sync(0xffffffffu, rs0, 2);
        rs1 += __shfl_xor_sync(0xffffffffu, rs1, 1);
        rs1 += __shfl_xor_sync(0xffffffffu, rs1, 2);
        l0 = l0 * al0 + rs0; l1 = l1 * al1 + rs1;
        #pragma unroll
        for (int n = 0; n < 16; n++) {
            o[n][0] *= al0; o[n][1] *= al0; o[n][2] *= al1; o[n][3] *= al1;
        }
        __syncwarp();   // P visible within owning warp

        // O += P @ V  (warp tile 16x128: 16 d-subtiles, 4 k16-steps over kv=64)
        #pragma unroll
        for (int ks = 0; ks < 4; ks++) {
            const int kk = ks * 16;
            uint32_t a0 = *(const uint32_t*)&Ps[r0*FPH + kk + 2*t];
            uint32_t a1 = *(const uint32_t*)&Ps[r1*FPH + kk + 2*t];
            uint32_t a2 = *(const uint32_t*)&Ps[r0*FPH + kk + 8 + 2*t];
            uint32_t a3 = *(const uint32_t*)&Ps[r1*FPH + kk + 8 + 2*t];
            #pragma unroll
            for (int n = 0; n < 16; n++) {
                const int col = n*8 + g;      // d column
                uint32_t b0 = *(const uint32_t*)&Vt[col*FVH + kk + 2*t];
                uint32_t b1 = *(const uint32_t*)&Vt[col*FVH + kk + 8 + 2*t];
                mma_f16(o[n][0], o[n][1], o[n][2], o[n][3], a0, a1, a2, a3, b0, b1);
            }
        }
    }

    // normalize + fp16 store O[b, q, h*128 + col]
    const float inv0 = 1.f / l0, inv1 = 1.f / l1;
    const long row0 = (long)(b*SEQ + q0 + r0);
    const long row1 = (long)(b*SEQ + q0 + r1);
    #pragma unroll
    for (int n = 0; n < 16; n++) {
        const int col = h*HDIM + n*8 + 2*t;
        *(__half2*)(O + row0*DMODEL + col) = __floats2half2_rn(o[n][0]*inv0, o[n][1]*inv0);
        *(__half2*)(O + row1*DMODEL + col) = __floats2half2_rn(o[n][2]*inv1, o[n][3]*inv1);
    }
}

// ---------------- launch ----------------
extern "C" void kernel_launch(void* const* d_in, const int* in_sizes, int n_in,
                              void* d_out, int out_size)
{
    const float* X        = (const float*)d_in[0];
    const float* Wq_down  = (const float*)d_in[1];
    const float* Wq_up    = (const float*)d_in[2];
    const float* Wkv_down = (const float*)d_in[3];
    const float* k_up     = (const float*)d_in[4];
    const float* v_up     = (const float*)d_in[5];
    const float* Wo       = (const float*)d_in[6];
    float* out = (float*)d_out;

    __half *xq, *q, *c, *kb, *vb, *vt, *ob, *kuT, *vuT;
    __half *xr, *wqdr, *wqur, *wkdr, *wor;
    cudaGetSymbolAddress((void**)&xq,  g_xq);
    cudaGetSymbolAddress((void**)&q,   g_q);
    cudaGetSymbolAddress((void**)&c,   g_c);
    cudaGetSymbolAddress((void**)&kb,  g_k);
    cudaGetSymbolAddress((void**)&vb,  g_v);
    cudaGetSymbolAddress((void**)&vt,  g_vt);
    cudaGetSymbolAddress((void**)&ob,  g_o);
    cudaGetSymbolAddress((void**)&kuT, g_kuT);
    cudaGetSymbolAddress((void**)&vuT, g_vuT);
    cudaGetSymbolAddress((void**)&xr,   g_xr);
    cudaGetSymbolAddress((void**)&wqdr, g_wqdr);
    cudaGetSymbolAddress((void**)&wqur, g_wqur);
    cudaGetSymbolAddress((void**)&wkdr, g_wkdr);
    cudaGetSymbolAddress((void**)&wor,  g_wor);

    cudaFuncSetAttribute(gemm_tc<0>, cudaFuncAttributeMaxDynamicSharedMemorySize, GEMM_SMEM_BYTES);
    cudaFuncSetAttribute(gemm_tc<2>, cudaFuncAttributeMaxDynamicSharedMemorySize, GEMM_SMEM_BYTES);
    cudaFuncSetAttribute(flash_tc,
                         cudaFuncAttributeMaxDynamicSharedMemorySize, FLASH_SMEM_BYTES);

    dim3 blk(256);
    dim3 blkG(128);
    const int ZBIG = 1 << 30;

    // 0) fp16-round all raw GEMM inputs
    round_half<<<512, blk>>>(X,        xr,   (long)MTOT*DMODEL/4);
    round_half<<<512, blk>>>(Wq_down,  wqdr, (long)RQ*DMODEL/4);
    round_half<<<512, blk>>>(Wq_up,    wqur, (long)DMODEL*RQ/4);
    round_half<<<512, blk>>>(Wkv_down, wkdr, (long)RKV*DMODEL/4);
    round_half<<<512, blk>>>(Wo,       wor,  (long)DMODEL*DMODEL/4);
    transpose_up<<<dim3(HDIM/32, RKV/32, NHEAD), blk>>>(k_up, kuT);
    transpose_up<<<dim3(HDIM/32, RKV/32, NHEAD), blk>>>(v_up, vuT);

    // 1) Xq = X @ Wq_down^T  (fp16 out)
    gemm_tc<2><<<dim3(RQ/128, MTOT/128, 1), blkG, GEMM_SMEM_BYTES>>>(
        xr, wqdr, xq, wqdr, xq, ZBIG, MTOT, RQ, DMODEL, 0, 0, 0, 1);
    // 2) Q = Xq @ Wq_up^T  (fp16 out, feeds flash)
    gemm_tc<2><<<dim3(DMODEL/128, MTOT/128, 1), blkG, GEMM_SMEM_BYTES>>>(
        xq, wqur, q, wqur, q, ZBIG, MTOT, DMODEL, RQ, 0, 0, 0, 1);
    // 3) C = X @ Wkv_down^T  (fp16 out)
    gemm_tc<2><<<dim3(RKV/128, MTOT/128, 1), blkG, GEMM_SMEM_BYTES>>>(
        xr, wkdr, c, wkdr, c, ZBIG, MTOT, RKV, DMODEL, 0, 0, 0, 1);
    // 4+5) merged K and V up-projections (fp16 out, natural [s,d] layout)
    gemm_tc<2><<<dim3(1, SEQ/128, 2*BATCH*NHEAD), blkG, GEMM_SMEM_BYTES>>>(
        c, kuT, kb, vuT, vb, BATCH*NHEAD, SEQ, HDIM, RKV,
        (long)SEQ*RKV, (long)HDIM*RKV, (long)SEQ*HDIM, NHEAD);
    // 5b) V -> V^T [b,h,d,s] (fp16)
    transpose_v<<<dim3(HDIM/32, SEQ/32, BATCH*NHEAD), blk>>>(vb, vt);
    // 6) fp16 flash attention (BM=128) -> ob (fp16)
    flash_tc<<<dim3(SEQ/128, BATCH*NHEAD), blk, FLASH_SMEM_BYTES>>>(q, kb, vt, ob);
    // 7) out = ob @ Wo^T : fp32 final output
    gemm_tc<0><<<dim3(DMODEL/128, MTOT/128, 1), blkG, GEMM_SMEM_BYTES>>>(
        ob, wor, out, wor, out, ZBIG, MTOT, DMODEL, DMODEL, 0, 0, 0, 1);
}